// round 1
// baseline (speedup 1.0000x reference)
#include <cuda_runtime.h>
#include <cuda_bf16.h>
#include <math.h>

// Problem constants (fixed by reference: x,y (4,2,32768) fp32, max_shift=128)
constexpr int T  = 32768;
constexpr int P  = 8;      // B*C pairs
constexpr int MS = 128;    // max_shift
constexpr int S  = 2 * MS + 1;  // 257 shifts

// Main-kernel tiling
constexpr int CHK    = 1024;        // time chunk per block
constexpr int NCHUNK = T / CHK;     // 32
constexpr int Z      = 4;           // time-slices per block
constexpr int G      = 65;          // shift groups of 4 -> covers shifts 0..259
constexpr int BD1    = Z * G;       // 260 threads

// Atomic-free partial buffer: [pair][chunk][shift (padded to 264)]
__device__ float g_part[P][NCHUNK][264];

// ---------------------------------------------------------------------------
// K1: raw shifted dot products  sxy(p,s) = sum_t x[t + s - MS] * y[t]
// (zero-padded x outside [0,T), matching reference's jnp.pad)
// ---------------------------------------------------------------------------
__global__ __launch_bounds__(BD1) void corr_main(const float* __restrict__ x,
                                                 const float* __restrict__ y) {
    __shared__ __align__(16) float smx[CHK + 264];  // x tile + halo (0..CHK+259 used)
    __shared__ __align__(16) float smy[CHK];
    __shared__ float red[Z][G][4];

    const int chunk = blockIdx.x;
    const int pair  = blockIdx.y;
    const float* xp = x + pair * T;
    const float* yp = y + pair * T;
    const int cbase = chunk * CHK;

    // Fill x tile: smx[i] = x_pad[cbase + i] where x_pad index = cbase - MS + i
    for (int i = threadIdx.x; i < CHK + 264; i += BD1) {
        int gi = cbase - MS + i;
        smx[i] = (gi >= 0 && gi < T) ? xp[gi] : 0.0f;
    }
    for (int i = threadIdx.x; i < CHK; i += BD1) {
        smy[i] = yp[cbase + i];
    }
    __syncthreads();

    const int g  = threadIdx.x % G;   // shift group: shifts [4g, 4g+4)
    const int tz = threadIdx.x / G;   // time slice
    const int t0 = tz * (CHK / Z);
    const int t1 = t0 + (CHK / Z);

    const float4* x4 = reinterpret_cast<const float4*>(smx);
    const float4* y4 = reinterpret_cast<const float4*>(smy);

    float a0 = 0.f, a1 = 0.f, a2 = 0.f, a3 = 0.f;
    int xi = (t0 + 4 * g) >> 2;
    float4 w0 = x4[xi];

    #pragma unroll 4
    for (int t = t0; t < t1; t += 4) {
        float4 w1 = x4[xi + 1];
        float4 yv = y4[t >> 2];
        // shift s = 4g + j : acc[j] += sum_k y[t+k] * smx[t + 4g + j + k]
        a0 += yv.x * w0.x + yv.y * w0.y + yv.z * w0.z + yv.w * w0.w;
        a1 += yv.x * w0.y + yv.y * w0.z + yv.z * w0.w + yv.w * w1.x;
        a2 += yv.x * w0.z + yv.y * w0.w + yv.z * w1.x + yv.w * w1.y;
        a3 += yv.x * w0.w + yv.y * w1.x + yv.z * w1.y + yv.w * w1.z;
        w0 = w1;
        xi++;
    }

    red[tz][g][0] = a0; red[tz][g][1] = a1;
    red[tz][g][2] = a2; red[tz][g][3] = a3;
    __syncthreads();

    if (threadIdx.x < G) {
        int gg = threadIdx.x;
        #pragma unroll
        for (int j = 0; j < 4; j++) {
            float s = red[0][gg][j] + red[1][gg][j] + red[2][gg][j] + red[3][gg][j];
            g_part[pair][chunk][4 * gg + j] = s;
        }
    }
}

// ---------------------------------------------------------------------------
// K2: per-pair stats + per-shift boundary corrections + final Pearson value
// out layout: (S, B, C) row-major -> out[s * P + pair]
// ---------------------------------------------------------------------------
__global__ __launch_bounds__(288) void corr_final(const float* __restrict__ x,
                                                  const float* __restrict__ y,
                                                  float* __restrict__ out) {
    const int pair = blockIdx.x;
    const float* xp = x + pair * T;
    const float* yp = y + pair * T;
    const int tid = threadIdx.x;

    // Full-array sums
    float sy = 0.f, syy = 0.f, sxs = 0.f, sxx = 0.f;
    for (int i = tid; i < T; i += 288) {
        float yv = yp[i], xv = xp[i];
        sy  += yv;  syy += yv * yv;
        sxs += xv;  sxx += xv * xv;
    }

    __shared__ float sm[4][9];
    __shared__ float tot[4];
    float v[4] = {sy, syy, sxs, sxx};
    const int lane = tid & 31;
    const int wrp  = tid >> 5;
    #pragma unroll
    for (int j = 0; j < 4; j++) {
        float t = v[j];
        for (int o = 16; o; o >>= 1) t += __shfl_down_sync(0xffffffffu, t, o);
        if (lane == 0) sm[j][wrp] = t;
    }
    __syncthreads();
    if (wrp == 0) {
        #pragma unroll
        for (int j = 0; j < 4; j++) {
            float t = (lane < 9) ? sm[j][lane] : 0.0f;
            for (int o = 16; o; o >>= 1) t += __shfl_down_sync(0xffffffffu, t, o);
            if (lane == 0) tot[j] = t;
        }
    }
    __syncthreads();

    const float Sy  = tot[0], Syy = tot[1];
    const float Sx  = tot[2], Sxx = tot[3];
    const float invT = 1.0f / (float)T;
    const float my   = Sy * invT;
    const float vyy  = Syy - my * Sy;   // sum((y - my)^2)

    const int s = tid;
    if (s < S) {
        float part = 0.f;
        #pragma unroll
        for (int c = 0; c < NCHUNK; c++) part += g_part[pair][c][s];

        // Window sums of x_pad over the shifted window = full sums minus the
        // head (d>0) or tail (d<0) that falls outside the window.
        const int d = s - MS;
        float bx = 0.f, bxx = 0.f;
        if (d > 0) {
            for (int i = 0; i < d; i++) { float vv = xp[i]; bx += vv; bxx += vv * vv; }
        } else if (d < 0) {
            for (int i = T + d; i < T; i++) { float vv = xp[i]; bx += vv; bxx += vv * vv; }
        }
        const float wsx  = Sx  - bx;
        const float wsxx = Sxx - bxx;

        const float num = part - my * wsx;            // sum(xw * yc)
        const float vxx = wsxx - wsx * wsx * invT;    // sum((xw - mean_xw)^2)
        out[s * P + pair] = num / sqrtf(vxx * vyy);
    }
}

extern "C" void kernel_launch(void* const* d_in, const int* in_sizes, int n_in,
                              void* d_out, int out_size) {
    const float* x = (const float*)d_in[0];
    const float* y = (const float*)d_in[1];
    float* out = (float*)d_out;

    corr_main<<<dim3(NCHUNK, P), BD1>>>(x, y);
    corr_final<<<P, 288>>>(x, y, out);
}

// round 2
// speedup vs baseline: 1.7966x; 1.7966x over previous
#include <cuda_runtime.h>
#include <cuda_bf16.h>
#include <math.h>

// Problem constants (fixed by reference: x,y (4,2,32768) fp32, max_shift=128)
constexpr int T  = 32768;
constexpr int P  = 8;      // B*C pairs
constexpr int MS = 128;    // max_shift
constexpr int S  = 2 * MS + 1;  // 257 shifts

// Main-kernel tiling
constexpr int CHK    = 1024;        // time chunk per block
constexpr int NCHUNK = T / CHK;     // 32
constexpr int Z      = 4;           // time-slices per block
constexpr int G      = 65;          // shift groups of 4 -> covers shifts 0..259
constexpr int BD1    = Z * G;       // 260 threads

// Atomic-free scratch: partial cross-correlations and per-chunk statistics
__device__ float g_part[P][NCHUNK][264];          // [pair][chunk][shift]
__device__ float g_stats[P][NCHUNK][4];           // [pair][chunk][{Sy,Syy,Sx,Sxx}]

// ---------------------------------------------------------------------------
// K1: raw shifted dot products  sxy(p,s) = sum_t x[t + s - MS] * y[t]
// (zero-padded x outside [0,T)) + per-chunk sums of x, x^2, y, y^2.
// ---------------------------------------------------------------------------
__global__ __launch_bounds__(BD1) void corr_main(const float* __restrict__ x,
                                                 const float* __restrict__ y) {
    __shared__ __align__(16) float smx[CHK + 264];  // x tile + halo
    __shared__ __align__(16) float smy[CHK];
    __shared__ float red[Z][G][4];
    __shared__ float wstats[8][4];

    const int chunk = blockIdx.x;
    const int pair  = blockIdx.y;
    const float* xp = x + pair * T;
    const float* yp = y + pair * T;
    const int cbase = chunk * CHK;

    // Fill x tile: smx[i] = x_pad[cbase + i], pad index = cbase - MS + i
    for (int i = threadIdx.x; i < CHK + 264; i += BD1) {
        int gi = cbase - MS + i;
        smx[i] = (gi >= 0 && gi < T) ? xp[gi] : 0.0f;
    }
    for (int i = threadIdx.x; i < CHK; i += BD1) {
        smy[i] = yp[cbase + i];
    }
    __syncthreads();

    // --- per-chunk statistics (first 256 threads = 8 full warps) ---
    if (threadIdx.x < 256) {
        float ly = 0.f, lyy = 0.f, lx = 0.f, lxx = 0.f;
        for (int i = threadIdx.x; i < CHK; i += 256) {
            float yv = smy[i];      ly  += yv; lyy += yv * yv;
            float xv = smx[MS + i]; lx  += xv; lxx += xv * xv;
        }
        #pragma unroll
        for (int o = 16; o; o >>= 1) {
            ly  += __shfl_down_sync(0xffffffffu, ly,  o);
            lyy += __shfl_down_sync(0xffffffffu, lyy, o);
            lx  += __shfl_down_sync(0xffffffffu, lx,  o);
            lxx += __shfl_down_sync(0xffffffffu, lxx, o);
        }
        if ((threadIdx.x & 31) == 0) {
            int w = threadIdx.x >> 5;
            wstats[w][0] = ly;  wstats[w][1] = lyy;
            wstats[w][2] = lx;  wstats[w][3] = lxx;
        }
    }

    // --- shifted dot products (all 260 threads) ---
    const int g  = threadIdx.x % G;   // shift group: shifts [4g, 4g+4)
    const int tz = threadIdx.x / G;   // time slice
    const int t0 = tz * (CHK / Z);
    const int t1 = t0 + (CHK / Z);

    const float4* x4 = reinterpret_cast<const float4*>(smx);
    const float4* y4 = reinterpret_cast<const float4*>(smy);

    float a0 = 0.f, a1 = 0.f, a2 = 0.f, a3 = 0.f;
    int xi = (t0 + 4 * g) >> 2;
    float4 w0 = x4[xi];

    #pragma unroll 4
    for (int t = t0; t < t1; t += 4) {
        float4 w1 = x4[xi + 1];
        float4 yv = y4[t >> 2];
        a0 += yv.x * w0.x + yv.y * w0.y + yv.z * w0.z + yv.w * w0.w;
        a1 += yv.x * w0.y + yv.y * w0.z + yv.z * w0.w + yv.w * w1.x;
        a2 += yv.x * w0.z + yv.y * w0.w + yv.z * w1.x + yv.w * w1.y;
        a3 += yv.x * w0.w + yv.y * w1.x + yv.z * w1.y + yv.w * w1.z;
        w0 = w1;
        xi++;
    }

    red[tz][g][0] = a0; red[tz][g][1] = a1;
    red[tz][g][2] = a2; red[tz][g][3] = a3;
    __syncthreads();

    if (threadIdx.x < G) {
        int gg = threadIdx.x;
        #pragma unroll
        for (int j = 0; j < 4; j++) {
            float s = red[0][gg][j] + red[1][gg][j] + red[2][gg][j] + red[3][gg][j];
            g_part[pair][chunk][4 * gg + j] = s;
        }
    }
    if (threadIdx.x >= G && threadIdx.x < G + 4) {
        int j = threadIdx.x - G;
        float s = 0.f;
        #pragma unroll
        for (int w = 0; w < 8; w++) s += wstats[w][j];
        g_stats[pair][chunk][j] = s;
    }
}

// ---------------------------------------------------------------------------
// K2: tiny finalize. Per pair: gather chunk stats (1 warp), load the 2*MS
// boundary elements of x into shared, then one thread per shift combines
// partials + boundary corrections into the Pearson value.
// out layout: (S, B, C) row-major -> out[s * P + pair]
// ---------------------------------------------------------------------------
constexpr int BD2 = 288;

__global__ __launch_bounds__(BD2) void corr_final(const float* __restrict__ x,
                                                  float* __restrict__ out) {
    __shared__ float bh[MS];   // x[0 .. MS)
    __shared__ float bt[MS];   // x[T-MS .. T)
    __shared__ float tot[4];

    const int pair = blockIdx.x;
    const float* xp = x + pair * T;
    const int tid = threadIdx.x;

    if (tid < MS)            bh[tid]      = xp[tid];
    else if (tid < 2 * MS)   bt[tid - MS] = xp[T - MS + (tid - MS)];

    // stats gather: warp 8 (threads 256..287, full warp)
    if (tid >= 256) {
        int c = tid - 256;   // chunk 0..31
        float4 v = *reinterpret_cast<const float4*>(g_stats[pair][c]);
        #pragma unroll
        for (int o = 16; o; o >>= 1) {
            v.x += __shfl_down_sync(0xffffffffu, v.x, o);
            v.y += __shfl_down_sync(0xffffffffu, v.y, o);
            v.z += __shfl_down_sync(0xffffffffu, v.z, o);
            v.w += __shfl_down_sync(0xffffffffu, v.w, o);
        }
        if (c == 0) { tot[0] = v.x; tot[1] = v.y; tot[2] = v.z; tot[3] = v.w; }
    }
    __syncthreads();

    const int s = tid;
    if (s < S) {
        const float Sy  = tot[0], Syy = tot[1];
        const float Sx  = tot[2], Sxx = tot[3];
        const float invT = 1.0f / (float)T;
        const float my   = Sy * invT;
        const float vyy  = Syy - my * Sy;       // sum((y - my)^2)

        float part = 0.f;
        #pragma unroll
        for (int c = 0; c < NCHUNK; c++) part += g_part[pair][c][s];

        // Window sums of padded x = full sums minus the out-of-window head/tail.
        const int d = s - MS;
        float bx = 0.f, bxx = 0.f;
        if (d > 0) {
            for (int i = 0; i < d; i++)      { float vv = bh[i]; bx += vv; bxx += vv * vv; }
        } else if (d < 0) {
            for (int i = MS + d; i < MS; i++){ float vv = bt[i]; bx += vv; bxx += vv * vv; }
        }
        const float wsx  = Sx  - bx;
        const float wsxx = Sxx - bxx;

        const float num = part - my * wsx;           // sum(xw * yc)
        const float vxx = wsxx - wsx * wsx * invT;   // sum((xw - mean_xw)^2)
        out[s * P + pair] = num / sqrtf(vxx * vyy);
    }
}

extern "C" void kernel_launch(void* const* d_in, const int* in_sizes, int n_in,
                              void* d_out, int out_size) {
    const float* x = (const float*)d_in[0];
    const float* y = (const float*)d_in[1];
    float* out = (float*)d_out;

    corr_main<<<dim3(NCHUNK, P), BD1>>>(x, y);
    corr_final<<<P, BD2>>>(x, out);
}